// round 15
// baseline (speedup 1.0000x reference)
#include <cuda_runtime.h>
#include <cuda_bf16.h>
#include <cstdint>

#define TS 96
#define NNODE 1024
#define GF 128
#define HID 512
#define NE 32768
#define INW 64
#define D2W 56
#define KFC (NNODE*GF)

// ---------------- static device scratch ----------------
__device__ float g_buf0[TS*NNODE*GF];   // GEMM outputs (pre-scaled by dinv)
__device__ float g_buf1[TS*NNODE*GF];   // message-passing outputs
__device__ int   g_ecnt[TS*NNODE];
__device__ int   g_offs[TS*NNODE];
__device__ float g_dinv[TS*NNODE];
__device__ int   g_csrc[TS*NE];
__device__ float g_gpre[TS*D2W];
__device__ float g_prega[TS*4*HID];
__device__ float g_Wht[4*HID*HID];
__device__ float g_Wit[INW*4*HID];      // [k][jp]
__device__ float g_Wgt[D2W*4*HID];      // [k][jp]
__device__ float g_bpre[4*HID];
__device__ float g_hbuf[2*HID];
__device__ unsigned g_bar;

// ---------------- helpers ----------------
__device__ __forceinline__ uint32_t pack_bf2(float a, float b) {
    __nv_bfloat162 h = __floats2bfloat162_rn(a, b);
    return *(uint32_t*)&h;
}
__device__ __forceinline__ void mma16816(float* c, const uint32_t* a, const uint32_t* b) {
    asm volatile(
        "mma.sync.aligned.m16n8k16.row.col.f32.bf16.bf16.f32 "
        "{%0,%1,%2,%3}, {%4,%5,%6,%7}, {%8,%9}, {%0,%1,%2,%3};\n"
        : "+f"(c[0]), "+f"(c[1]), "+f"(c[2]), "+f"(c[3])
        : "r"(a[0]), "r"(a[1]), "r"(a[2]), "r"(a[3]), "r"(b[0]), "r"(b[1]));
}

// ---------------- init ----------------
__global__ void k_init() {
    int idx = blockIdx.x*blockDim.x + threadIdx.x;
    if (idx < TS*D2W) g_gpre[idx] = 0.f;
    if (idx < 2*HID)  g_hbuf[idx] = 0.f;
    if (idx == 0)     g_bar = 0u;
}

// ---------------- fused graph prep: histogram + scan + CSR fill in SMEM ----------------
__global__ __launch_bounds__(1024)
void k_graph(const int* __restrict__ ei) {
    int t = blockIdx.x, tid = threadIdx.x;
    __shared__ int scnt[NNODE];
    __shared__ int soff[NNODE];
    const int* srcp = ei + t*2*NE;
    const int* dstp = ei + t*2*NE + NE;

    scnt[tid] = 0;
    __syncthreads();
    #pragma unroll
    for (int i = 0; i < NE/NNODE; i++)
        atomicAdd(&scnt[dstp[i*NNODE + tid] & (NNODE-1)], 1);
    __syncthreads();

    int c = scnt[tid];
    g_ecnt[t*NNODE + tid] = c;
    g_dinv[t*NNODE + tid] = rsqrtf((float)(c + 1));

    soff[tid] = c;
    for (int off = 1; off < NNODE; off <<= 1) {
        __syncthreads();
        int v = (tid >= off) ? soff[tid - off] : 0;
        __syncthreads();
        soff[tid] += v;
    }
    __syncthreads();
    int excl = soff[tid] - c;
    g_offs[t*NNODE + tid] = excl;
    scnt[tid] = excl;
    __syncthreads();

    #pragma unroll
    for (int i = 0; i < NE/NNODE; i++) {
        int e   = i*NNODE + tid;
        int src = srcp[e] & (NNODE-1);
        int dst = dstp[e] & (NNODE-1);
        int pos = atomicAdd(&scnt[dst], 1);
        g_csrc[(size_t)t*NE + pos] = src;
    }
}

// ---------------- bf16-split tensor-core GEMM (R11 verbatim + register prefetch) ----------------
// g_buf0[t][n] = (A[t] @ B)[n] * dinv[t][n],  via Ahi@Bhi + Ahi@Blo + Alo@Bhi
template<bool FIRST>
__global__ __launch_bounds__(256)
void k_gemm_tc(const float* __restrict__ Aext, const float* __restrict__ B) {
    constexpr int K = FIRST ? NNODE : GF;
    const int t  = blockIdx.y;
    const int m0 = blockIdx.x * 128;
    const float* At = (FIRST ? Aext : (const float*)g_buf1) + (size_t)t * NNODE * K;
    float*       Ct = g_buf0 + (size_t)t * NNODE * GF;

    __shared__ uint32_t As32[2][128][18];   // [hi/lo][row][kpair+pad]
    __shared__ uint32_t Bs32[2][128][18];

    const int tid  = threadIdx.x;
    const int lane = tid & 31, wid = tid >> 5;
    const int mbase = (wid >> 1) * 32;
    const int nbase = (wid & 1) * 64;
    const int r = lane >> 2, q = lane & 3;

    float c[2][8][4];
    #pragma unroll
    for (int mt = 0; mt < 2; mt++)
        #pragma unroll
        for (int nt = 0; nt < 8; nt++)
            #pragma unroll
            for (int i = 0; i < 4; i++) c[mt][nt][i] = 0.f;

    // register prefetch buffers
    float4 pa[4];
    float4 pb0[2], pb1[2];

    // prefetch tile 0
    #pragma unroll
    for (int it = 0; it < 4; it++) {
        int idx = tid + it*256;
        int row = idx >> 3, c4 = idx & 7;
        pa[it] = *(const float4*)(At + (size_t)(m0 + row)*K + c4*4);
    }
    #pragma unroll
    for (int it = 0; it < 2; it++) {
        int n4 = tid & 31;
        int kp = (tid >> 5) + it*8;
        const float* bp = B + (size_t)(kp*2)*GF + n4*4;
        pb0[it] = *(const float4*)(bp);
        pb1[it] = *(const float4*)(bp + GF);
    }

    for (int kk = 0; kk < K; kk += 32) {
        // ---- stage registers -> smem (R11 conversion code) ----
        #pragma unroll
        for (int it = 0; it < 4; it++) {
            int idx = tid + it*256;
            int row = idx >> 3, c4 = idx & 7;
            float4 v = pa[it];
            float hx = __bfloat162float(__float2bfloat16(v.x));
            float hy = __bfloat162float(__float2bfloat16(v.y));
            float hz = __bfloat162float(__float2bfloat16(v.z));
            float hw = __bfloat162float(__float2bfloat16(v.w));
            As32[0][row][c4*2]   = pack_bf2(hx, hy);
            As32[0][row][c4*2+1] = pack_bf2(hz, hw);
            As32[1][row][c4*2]   = pack_bf2(v.x - hx, v.y - hy);
            As32[1][row][c4*2+1] = pack_bf2(v.z - hz, v.w - hw);
        }
        #pragma unroll
        for (int it = 0; it < 2; it++) {
            int n4 = tid & 31;
            int kp = (tid >> 5) + it*8;
            float a0[4] = {pb0[it].x, pb0[it].y, pb0[it].z, pb0[it].w};
            float a1[4] = {pb1[it].x, pb1[it].y, pb1[it].z, pb1[it].w};
            #pragma unroll
            for (int j = 0; j < 4; j++) {
                float h0 = __bfloat162float(__float2bfloat16(a0[j]));
                float h1 = __bfloat162float(__float2bfloat16(a1[j]));
                Bs32[0][n4*4 + j][kp] = pack_bf2(h0, h1);
                Bs32[1][n4*4 + j][kp] = pack_bf2(a0[j] - h0, a1[j] - h1);
            }
        }
        __syncthreads();
        // ---- prefetch next tile into registers (overlaps with compute below) ----
        if (kk + 32 < K) {
            int kk2 = kk + 32;
            #pragma unroll
            for (int it = 0; it < 4; it++) {
                int idx = tid + it*256;
                int row = idx >> 3, c4 = idx & 7;
                pa[it] = *(const float4*)(At + (size_t)(m0 + row)*K + kk2 + c4*4);
            }
            #pragma unroll
            for (int it = 0; it < 2; it++) {
                int n4 = tid & 31;
                int kp = (tid >> 5) + it*8;
                const float* bp = B + (size_t)(kk2 + kp*2)*GF + n4*4;
                pb0[it] = *(const float4*)(bp);
                pb1[it] = *(const float4*)(bp + GF);
            }
        }
        // ---- compute (R11 verbatim) ----
        #pragma unroll
        for (int s = 0; s < 2; s++) {
            uint32_t af[2][2][4];
            #pragma unroll
            for (int mt = 0; mt < 2; mt++) {
                int mrow = mbase + mt*16 + r;
                af[mt][0][0] = As32[0][mrow][s*8 + q];
                af[mt][0][1] = As32[0][mrow + 8][s*8 + q];
                af[mt][0][2] = As32[0][mrow][s*8 + q + 4];
                af[mt][0][3] = As32[0][mrow + 8][s*8 + q + 4];
                af[mt][1][0] = As32[1][mrow][s*8 + q];
                af[mt][1][1] = As32[1][mrow + 8][s*8 + q];
                af[mt][1][2] = As32[1][mrow][s*8 + q + 4];
                af[mt][1][3] = As32[1][mrow + 8][s*8 + q + 4];
            }
            #pragma unroll
            for (int nt = 0; nt < 8; nt++) {
                int nrow = nbase + nt*8 + r;
                uint32_t bhf[2] = { Bs32[0][nrow][s*8 + q], Bs32[0][nrow][s*8 + q + 4] };
                uint32_t blf[2] = { Bs32[1][nrow][s*8 + q], Bs32[1][nrow][s*8 + q + 4] };
                #pragma unroll
                for (int mt = 0; mt < 2; mt++) {
                    mma16816(c[mt][nt], af[mt][0], bhf);   // hi*hi
                    mma16816(c[mt][nt], af[mt][0], blf);   // hi*lo
                    mma16816(c[mt][nt], af[mt][1], bhf);   // lo*hi
                }
            }
        }
        __syncthreads();
    }

    // epilogue: scale rows by dinv, fp32 store (R11 verbatim)
    #pragma unroll
    for (int mt = 0; mt < 2; mt++) {
        int row0 = m0 + mbase + mt*16 + r;
        float d0 = g_dinv[t*NNODE + row0];
        float d1 = g_dinv[t*NNODE + row0 + 8];
        #pragma unroll
        for (int nt = 0; nt < 8; nt++) {
            int col = nbase + nt*8 + 2*q;
            *(float2*)(Ct + (size_t)row0*GF + col)       = make_float2(c[mt][nt][0]*d0, c[mt][nt][1]*d0);
            *(float2*)(Ct + (size_t)(row0 + 8)*GF + col) = make_float2(c[mt][nt][2]*d1, c[mt][nt][3]*d1);
        }
    }
}

// ---------------- GCN message passing: warp-per-node, float4 rows ----------------
template<bool RELU>
__global__ __launch_bounds__(256)
void k_mp(const float* __restrict__ bias) {
    int t    = blockIdx.y;
    int warp = threadIdx.x >> 5, lane = threadIdx.x & 31;
    int n    = blockIdx.x*8 + warp;
    const float4* Zt = (const float4*)(g_buf0 + (size_t)t * NNODE * GF);
    const int*    cs = g_csrc + (size_t)t*NE;

    float4 z = Zt[n*32 + lane];
    float a0 = z.x, a1 = z.y, a2 = z.z, a3 = z.w;
    float b0 = 0.f, b1 = 0.f, b2 = 0.f, b3 = 0.f;

    int e   = g_offs[t*NNODE + n];
    int end = e + g_ecnt[t*NNODE + n];
    for (; e + 1 < end; e += 2) {
        int s0 = cs[e], s1 = cs[e+1];
        float4 z0 = Zt[s0*32 + lane];
        float4 z1 = Zt[s1*32 + lane];
        a0 += z0.x; a1 += z0.y; a2 += z0.z; a3 += z0.w;
        b0 += z1.x; b1 += z1.y; b2 += z1.z; b3 += z1.w;
    }
    if (e < end) {
        int s = cs[e];
        float4 z0 = Zt[s*32 + lane];
        a0 += z0.x; a1 += z0.y; a2 += z0.z; a3 += z0.w;
    }
    float dn = g_dinv[t*NNODE + n];
    float4 bi = ((const float4*)bias)[lane];
    float4 o;
    o.x = (a0 + b0)*dn + bi.x;
    o.y = (a1 + b1)*dn + bi.y;
    o.z = (a2 + b2)*dn + bi.z;
    o.w = (a3 + b3)*dn + bi.w;
    if (RELU) {
        o.x = fmaxf(o.x, 0.f); o.y = fmaxf(o.y, 0.f);
        o.z = fmaxf(o.z, 0.f); o.w = fmaxf(o.w, 0.f);
    }
    ((float4*)(g_buf1 + (size_t)t*NNODE*GF))[n*32 + lane] = o;
}

// ---------------- FC: g_gpre[96][56] += g_buf1 @ Wfc (K-split) ----------------
__global__ void k_fc(const float* __restrict__ Wfc) {
    const float* Xh = g_buf1;
    __shared__ float As[96][65];
    __shared__ float Ws[64][57];
    int tid = threadIdx.x;
    int tt = tid >> 3, dd = tid & 7;
    int k0 = blockIdx.x * 512;
    float acc[3][7];
    #pragma unroll
    for (int r = 0; r < 3; r++)
        #pragma unroll
        for (int j = 0; j < 7; j++) acc[r][j] = 0.f;

    for (int sub = 0; sub < 8; sub++) {
        int kk = k0 + sub*64;
        for (int i = tid; i < 96*64; i += 256) {
            int tr = i >> 6, kl = i & 63;
            As[tr][kl] = Xh[(size_t)tr*KFC + kk + kl];
        }
        for (int i = tid; i < 64*56; i += 256) {
            int kl = i / 56, d = i - kl*56;
            Ws[kl][d] = Wfc[(size_t)(kk + kl)*56 + d];
        }
        __syncthreads();
        for (int k = 0; k < 64; k++) {
            float a0 = As[tt*3+0][k], a1 = As[tt*3+1][k], a2 = As[tt*3+2][k];
            #pragma unroll
            for (int j = 0; j < 7; j++) {
                float w = Ws[k][dd*7 + j];
                acc[0][j] += a0*w; acc[1][j] += a1*w; acc[2][j] += a2*w;
            }
        }
        __syncthreads();
    }
    #pragma unroll
    for (int r = 0; r < 3; r++)
        #pragma unroll
        for (int j = 0; j < 7; j++)
            atomicAdd(&g_gpre[(tt*3 + r)*D2W + dd*7 + j], acc[r][j]);
}

// ---------------- transpose LSTM weights ----------------
__global__ void k_trans(const float* __restrict__ Wii, const float* __restrict__ Wgi,
                        const float* __restrict__ Whi, const float* __restrict__ bi,
                        const float* __restrict__ Wif, const float* __restrict__ Wgf,
                        const float* __restrict__ Whf, const float* __restrict__ bf,
                        const float* __restrict__ Wig, const float* __restrict__ Wgg,
                        const float* __restrict__ Whg, const float* __restrict__ bg,
                        const float* __restrict__ Wio, const float* __restrict__ Wgo,
                        const float* __restrict__ Who, const float* __restrict__ bo) {
    int jp   = blockIdx.x;
    int col  = jp >> 2;
    int gate = jp & 3;
    const float* Wh = (gate == 0) ? Whi : (gate == 1) ? Whf : (gate == 2) ? Whg : Who;
    const float* Wi = (gate == 0) ? Wii : (gate == 1) ? Wif : (gate == 2) ? Wig : Wio;
    const float* Wg = (gate == 0) ? Wgi : (gate == 1) ? Wgf : (gate == 2) ? Wgg : Wgo;
    const float* bb = (gate == 0) ? bi  : (gate == 1) ? bf  : (gate == 2) ? bg  : bo;
    for (int k = threadIdx.x; k < HID; k += blockDim.x)
        g_Wht[(size_t)jp*HID + k] = Wh[(size_t)k*HID + col];
    if (threadIdx.x < INW) g_Wit[threadIdx.x*4*HID + jp] = Wi[threadIdx.x*HID + col];
    if (threadIdx.x < D2W) g_Wgt[threadIdx.x*4*HID + jp] = Wg[threadIdx.x*HID + col];
    if (threadIdx.x == 0)  g_bpre[jp] = bb[col];
}

// ---------------- input-side gate preactivations ----------------
__global__ void k_pre(const float* __restrict__ x_in, const float* __restrict__ bfc) {
    int t  = blockIdx.y;
    int jp = blockIdx.x*blockDim.x + threadIdx.x;
    __shared__ float xg[INW];
    __shared__ float gg[D2W];
    if (threadIdx.x < INW) xg[threadIdx.x] = x_in[t*INW + threadIdx.x];
    if (threadIdx.x < D2W)
        gg[threadIdx.x] = fmaxf(g_gpre[t*D2W + threadIdx.x] + bfc[threadIdx.x], 0.f);
    __syncthreads();
    float acc = g_bpre[jp];
    #pragma unroll
    for (int k = 0; k < INW; k++) acc += xg[k] * g_Wit[k*4*HID + jp];
    #pragma unroll
    for (int k = 0; k < D2W; k++) acc += gg[k] * g_Wgt[k*4*HID + jp];
    g_prega[t*4*HID + jp] = acc;
}

// ---------------- persistent LSTM ----------------
__device__ __forceinline__ float sigm(float x) { return 1.f / (1.f + expf(-x)); }

__global__ __launch_bounds__(256, 1)
void k_lstm(float* __restrict__ out, int write_hc) {
    int tid = threadIdx.x, b = blockIdx.x;
    int o_local = tid >> 3;
    int s       = tid & 7;
    int jp      = b*32 + o_local;
    float w[64];
    #pragma unroll
    for (int j = 0; j < 64; j++)
        w[j] = g_Wht[(size_t)jp*HID + j*8 + s];

    __shared__ float h_sh[HID];
    __shared__ float gates_sh[32];
    __shared__ float c_sh[8];
    if (tid < 8) c_sh[tid] = 0.f;

    for (int t = 0; t < TS; t++) {
        h_sh[tid]       = g_hbuf[(t & 1)*HID + tid];
        h_sh[tid + 256] = g_hbuf[(t & 1)*HID + tid + 256];
        __syncthreads();
        float acc = 0.f;
        #pragma unroll
        for (int j = 0; j < 64; j++) acc += w[j] * h_sh[j*8 + s];
        acc += __shfl_down_sync(0xffffffffu, acc, 4);
        acc += __shfl_down_sync(0xffffffffu, acc, 2);
        acc += __shfl_down_sync(0xffffffffu, acc, 1);
        if (s == 0) gates_sh[o_local] = acc + g_prega[t*4*HID + jp];
        __syncthreads();
        if (tid < 8) {
            float gi = gates_sh[tid*4 + 0];
            float gf = gates_sh[tid*4 + 1];
            float gc = gates_sh[tid*4 + 2];
            float go = gates_sh[tid*4 + 3];
            float i_ = sigm(gi), f_ = sigm(gf), o_ = sigm(go);
            float cc = f_*c_sh[tid] + i_*tanhf(gc);
            c_sh[tid] = cc;
            float h = o_*tanhf(cc);
            int col = b*8 + tid;
            g_hbuf[((t + 1) & 1)*HID + col] = h;
            out[t*HID + col] = h;
            if (t == TS - 1 && write_hc) {
                out[TS*HID + col]       = h;
                out[TS*HID + HID + col] = cc;
            }
        }
        __syncthreads();
        if (tid == 0) {
            __threadfence();
            atomicAdd(&g_bar, 1u);
            unsigned target = (unsigned)(t + 1) * 64u;
            while (*(volatile unsigned*)&g_bar < target) __nanosleep(32);
            __threadfence();
        }
        __syncthreads();
    }
}

// ---------------- host launch (slot 4 = k_gemm_tc<true> for ncu) ----------------
extern "C" void kernel_launch(void* const* d_in, const int* in_sizes, int n_in,
                              void* d_out, int out_size) {
    const float* input  = (const float*)d_in[0];
    const float* xnodes = (const float*)d_in[1];
    const int*   ei     = (const int*)d_in[2];
    const float* W1  = (const float*)d_in[3];
    const float* b1  = (const float*)d_in[4];
    const float* W2  = (const float*)d_in[5];
    const float* b2  = (const float*)d_in[6];
    const float* Wfc = (const float*)d_in[7];
    const float* bfc = (const float*)d_in[8];
    const float* Wii = (const float*)d_in[9],  *Wgi = (const float*)d_in[10];
    const float* Whi = (const float*)d_in[11], *bi  = (const float*)d_in[12];
    const float* Wif = (const float*)d_in[13], *Wgf = (const float*)d_in[14];
    const float* Whf = (const float*)d_in[15], *bf  = (const float*)d_in[16];
    const float* Wig = (const float*)d_in[17], *Wgg = (const float*)d_in[18];
    const float* Whg = (const float*)d_in[19], *bg  = (const float*)d_in[20];
    const float* Wio = (const float*)d_in[21], *Wgo = (const float*)d_in[22];
    const float* Who = (const float*)d_in[23], *bo  = (const float*)d_in[24];
    float* out = (float*)d_out;

    k_init<<<24, 256>>>();                                      // 1
    k_graph<<<TS, NNODE>>>(ei);                                 // 2
    k_trans<<<4*HID, 128>>>(Wii, Wgi, Whi, bi, Wif, Wgf, Whf, bf,
                            Wig, Wgg, Whg, bg, Wio, Wgo, Who, bo); // 3
    k_gemm_tc<true><<<dim3(8, TS), 256>>>(xnodes, W1);          // 4 <- ncu slot
    k_mp<true><<<dim3(NNODE/8, TS), 256>>>(b1);                 // 5
    k_gemm_tc<false><<<dim3(8, TS), 256>>>(nullptr, W2);        // 6
    k_mp<false><<<dim3(NNODE/8, TS), 256>>>(b2);                // 7
    k_fc<<<256, 256>>>(Wfc);                                    // 8
    k_pre<<<dim3(8, TS), 256>>>(input, bfc);                    // 9
    int whc = (out_size >= TS*HID + 2*HID) ? 1 : 0;
    k_lstm<<<64, 256>>>(out, whc);                              // 10
}